// round 9
// baseline (speedup 1.0000x reference)
#include <cuda_runtime.h>

// ProdAt: x [16384, 8192] fp32 -> out [16384, 128] fp32
// out[seg] = prod of 64 contiguous floats.
//
// R9: LDG.256 x 4 segments/thread — maximum bytes-in-flight per instruction.
//   8 lanes per segment; each lane loads one 32B v8 chunk, so a single
//   LDG.256 by an 8-lane group covers an entire 256B segment.
//   Each thread handles 4 segments (2 adjacent pairs) -> 4 front-batched
//   LDG.256 = 128B/thread in flight from 4 instructions.
//   3-step shfl_xor reduce per segment; sub==0 lanes store 2x packed float2.

static constexpr long long N_SEGMENTS_TOTAL = 16384LL * 128LL;  // 2,097,152

struct f8 { float v[8]; };

__device__ __forceinline__ f8 ldg_v8(const float* p) {
    f8 r;
    asm volatile(
        "ld.global.nc.L1::evict_first.L2::256B.v8.f32 "
        "{%0,%1,%2,%3,%4,%5,%6,%7}, [%8];"
        : "=f"(r.v[0]), "=f"(r.v[1]), "=f"(r.v[2]), "=f"(r.v[3]),
          "=f"(r.v[4]), "=f"(r.v[5]), "=f"(r.v[6]), "=f"(r.v[7])
        : "l"(p));
    return r;
}

__device__ __forceinline__ float prod8(const f8& a) {
    return ((a.v[0] * a.v[1]) * (a.v[2] * a.v[3])) *
           ((a.v[4] * a.v[5]) * (a.v[6] * a.v[7]));
}

__global__ void __launch_bounds__(512) prodat_kernel(
    const float* __restrict__ x, float* __restrict__ out)
{
    const long long warp_id =
        (long long)blockIdx.x * (blockDim.x >> 5) + (threadIdx.x >> 5);
    const int lane = threadIdx.x & 31;

    const int g   = lane >> 3;   // 0..3 : segment-pair group within warp
    const int sub = lane & 7;    // 0..7 : 32B slot within segment

    // warp covers 16 consecutive segments [warp_id*16, warp_id*16+16)
    // this thread: adjacent pairs (2g, 2g+1) and (2g+8, 2g+9)
    const long long s0 = warp_id * 16 + 2 * g;
    const long long s1 = s0 + 1;
    const long long s2 = s0 + 8;
    const long long s3 = s2 + 1;

    // front-batch 4 independent 256-bit loads (128B/thread in flight)
    const f8 a0 = ldg_v8(x + s0 * 64 + sub * 8);
    const f8 a1 = ldg_v8(x + s1 * 64 + sub * 8);
    const f8 a2 = ldg_v8(x + s2 * 64 + sub * 8);
    const f8 a3 = ldg_v8(x + s3 * 64 + sub * 8);

    float p0 = prod8(a0);
    float p1 = prod8(a1);
    float p2 = prod8(a2);
    float p3 = prod8(a3);

    // four independent 3-step reductions over the 8-lane group (pipelined)
    #pragma unroll
    for (int off = 4; off > 0; off >>= 1) {
        p0 *= __shfl_xor_sync(0xffffffffu, p0, off);
        p1 *= __shfl_xor_sync(0xffffffffu, p1, off);
        p2 *= __shfl_xor_sync(0xffffffffu, p2, off);
        p3 *= __shfl_xor_sync(0xffffffffu, p3, off);
    }

    if (sub == 0) {
        float2* out2 = reinterpret_cast<float2*>(out);
        out2[s0 >> 1] = make_float2(p0, p1);   // STG.64
        out2[s2 >> 1] = make_float2(p2, p3);   // STG.64
    }
}

extern "C" void kernel_launch(void* const* d_in, const int* in_sizes, int n_in,
                              void* d_out, int out_size)
{
    const float* x = (const float*)d_in[0];
    float* out = (float*)d_out;

    // 512 threads = 16 warps = 256 segments per block
    const int threads = 512;
    const long long blocks = N_SEGMENTS_TOTAL / 256;  // 8192, exact

    prodat_kernel<<<(unsigned)blocks, threads>>>(x, out);
}

// round 10
// speedup vs baseline: 1.0143x; 1.0143x over previous
#include <cuda_runtime.h>

// ProdAt: x [16384, 8192] fp32 -> out [16384, 128] fp32
// out[seg] = prod of 64 contiguous floats.
//
// FINAL (best measured, R5 config; 80.0us wall, ~6.9TB/s = measured LTS cap):
//   8 lanes per segment; each lane loads f4[sub] and f4[sub+8] (each LDG.128
//   by an 8-lane group covers one full 128B line -> perfect coalescing).
//   Each thread handles 2 ADJACENT segments -> 4 independent LDG.128
//   front-batched (MLP=4); sub==0 lanes store a packed float2 (STG.64,
//   fully-covered 32B write sectors per warp). 512-thread blocks.
//
// Exhaustive search (R2-R9: MLP 4/8, 128/256-bit loads, 256/512 threads,
// persistent grid, L2::256B hints) all pinned at 6.87-6.97 TB/s — the
// path-independent LTS byte cap (~6300 B/cyc). This op is structurally
// bound there; this variant had the best wall time.

static constexpr long long N_SEGMENTS_TOTAL = 16384LL * 128LL;  // 2,097,152

__device__ __forceinline__ float prod4(float4 v) {
    return (v.x * v.y) * (v.z * v.w);
}

__global__ void __launch_bounds__(512) prodat_kernel(
    const float* __restrict__ x, float* __restrict__ out)
{
    const long long warp_id =
        (long long)blockIdx.x * (blockDim.x >> 5) + (threadIdx.x >> 5);
    const int lane = threadIdx.x & 31;

    const int g   = lane >> 3;   // 0..3 : segment-pair group within warp
    const int sub = lane & 7;    // 0..7 : float4 slot within segment half

    // warp covers 8 consecutive segments [warp_id*8, warp_id*8+8)
    // this thread: adjacent segments 2g and 2g+1
    const long long seg0 = warp_id * 8 + 2 * g;
    const long long seg1 = seg0 + 1;

    const float4* x4 = reinterpret_cast<const float4*>(x);

    // front-batch 4 independent loads (MLP = 4), streaming eviction
    const float4 a0 = __ldcs(x4 + seg0 * 16 + sub);
    const float4 b0 = __ldcs(x4 + seg0 * 16 + 8 + sub);
    const float4 a1 = __ldcs(x4 + seg1 * 16 + sub);
    const float4 b1 = __ldcs(x4 + seg1 * 16 + 8 + sub);

    float p0 = prod4(a0) * prod4(b0);
    float p1 = prod4(a1) * prod4(b1);

    // two independent 3-step reductions over the 8-lane group (pipelined)
    #pragma unroll
    for (int off = 4; off > 0; off >>= 1) {
        p0 *= __shfl_xor_sync(0xffffffffu, p0, off);
        p1 *= __shfl_xor_sync(0xffffffffu, p1, off);
    }

    if (sub == 0) {
        // packed 8B store of two adjacent segment results (STG.64)
        reinterpret_cast<float2*>(out)[seg0 >> 1] = make_float2(p0, p1);
    }
}

extern "C" void kernel_launch(void* const* d_in, const int* in_sizes, int n_in,
                              void* d_out, int out_size)
{
    const float* x = (const float*)d_in[0];
    float* out = (float*)d_out;

    // 512 threads = 16 warps = 128 segments per block
    const int threads = 512;
    const long long blocks = N_SEGMENTS_TOTAL / 128;  // 16384, exact

    prodat_kernel<<<(unsigned)blocks, threads>>>(x, out);
}

// round 11
// speedup vs baseline: 1.0661x; 1.0510x over previous
#include <cuda_runtime.h>

// ProdAt: x [16384, 8192] fp32 -> out [16384, 128] fp32
// out[seg] = prod of 64 contiguous floats.
//
// R11 (last matrix cell): R2's 256-thread blocks (highest measured GB/s,
// 6973) combined with R5's adjacent-pair packed stores.
//   8 lanes per segment; each lane loads f4[sub] and f4[sub+8] (each LDG.128
//   by an 8-lane group covers one full 128B line -> perfect coalescing).
//   Each thread handles 2 ADJACENT segments -> 4 independent LDG.128
//   front-batched (MLP=4); sub==0 lanes store a packed float2 (STG.64).

static constexpr long long N_SEGMENTS_TOTAL = 16384LL * 128LL;  // 2,097,152

__device__ __forceinline__ float prod4(float4 v) {
    return (v.x * v.y) * (v.z * v.w);
}

__global__ void __launch_bounds__(256) prodat_kernel(
    const float* __restrict__ x, float* __restrict__ out)
{
    const long long warp_id =
        (long long)blockIdx.x * (blockDim.x >> 5) + (threadIdx.x >> 5);
    const int lane = threadIdx.x & 31;

    const int g   = lane >> 3;   // 0..3 : segment-pair group within warp
    const int sub = lane & 7;    // 0..7 : float4 slot within segment half

    // warp covers 8 consecutive segments [warp_id*8, warp_id*8+8)
    // this thread: adjacent segments 2g and 2g+1
    const long long seg0 = warp_id * 8 + 2 * g;
    const long long seg1 = seg0 + 1;

    const float4* x4 = reinterpret_cast<const float4*>(x);

    // front-batch 4 independent loads (MLP = 4), streaming eviction
    const float4 a0 = __ldcs(x4 + seg0 * 16 + sub);
    const float4 b0 = __ldcs(x4 + seg0 * 16 + 8 + sub);
    const float4 a1 = __ldcs(x4 + seg1 * 16 + sub);
    const float4 b1 = __ldcs(x4 + seg1 * 16 + 8 + sub);

    float p0 = prod4(a0) * prod4(b0);
    float p1 = prod4(a1) * prod4(b1);

    // two independent 3-step reductions over the 8-lane group (pipelined)
    #pragma unroll
    for (int off = 4; off > 0; off >>= 1) {
        p0 *= __shfl_xor_sync(0xffffffffu, p0, off);
        p1 *= __shfl_xor_sync(0xffffffffu, p1, off);
    }

    if (sub == 0) {
        // packed 8B store of two adjacent segment results (STG.64)
        reinterpret_cast<float2*>(out)[seg0 >> 1] = make_float2(p0, p1);
    }
}

extern "C" void kernel_launch(void* const* d_in, const int* in_sizes, int n_in,
                              void* d_out, int out_size)
{
    const float* x = (const float*)d_in[0];
    float* out = (float*)d_out;

    // 256 threads = 8 warps = 64 segments per block
    const int threads = 256;
    const long long blocks = N_SEGMENTS_TOTAL / 64;  // 32768, exact

    prodat_kernel<<<(unsigned)blocks, threads>>>(x, out);
}